// round 11
// baseline (speedup 1.0000x reference)
#include <cuda_runtime.h>
#include <cuda_fp16.h>

#define D 256
#define MAXN 100000
#define MAXNET 50176
#define MAXE 301056
#define BM 64
#define KT 16
#define PAH 24       // A row stride (halves): word 12g+t -> conflict-free
#define PBH 24       // B row stride (halves): word 12n+t -> conflict-free
#define PHH 264      // hid row stride (halves): word 132m -> 4g+t distinct

#define ASZH (BM * PAH)       // 1536 halves per A buffer
#define BSZH (256 * PBH)      // 6144 halves per B buffer
#define HIDH (BM * PHH)       // 16896 halves
#define SM_BS_H (2 * ASZH)
#define SM_HID_H (2 * ASZH + 2 * BSZH)
#define SMEM_BYTES ((2 * ASZH + 2 * BSZH + HIDH) * 2)   // 64512 B

// Scratch (allocation-free rule: __device__ globals)
__device__ __half g_ch16[(size_t)MAXN * D];     // cell_h fp16
__device__ __half g_nh16[(size_t)MAXNET * D];   // net_h fp16
__device__ __half g_on16[(size_t)MAXNET * D];   // out_net fp16
__device__ __half g_tp16[(size_t)MAXN * D];     // stage2 out fp16
__device__ __half g_mg16[(size_t)MAXN * D];     // msg fp16
__device__ __half g_w1h[512 * 256];             // W1 fp16, [n][k]
__device__ __half g_w2h[256 * 256];             // W2 fp16, [n][k]
__device__ float  g_tmp[(size_t)MAXN * D];      // stage2 out fp32 (residual)
__device__ int    g_offs[MAXN + 1];
__device__ int    g_cur[MAXN];
__device__ int    g_eid[MAXE];
__device__ int    g_aux[128];
__device__ int    g_total;

// ---------------------------------------------------------------------------
// fp32 -> fp16 elementwise (n multiple of 4)
__global__ void cvt_h16_kernel(const float* __restrict__ in,
                               __half* __restrict__ out, int n4) {
    int i = blockIdx.x * blockDim.x + threadIdx.x;
    if (i >= n4) return;
    float4 v = ((const float4*)in)[i];
    __half2 h0 = __floats2half2_rn(v.x, v.y);
    __half2 h1 = __floats2half2_rn(v.z, v.w);
    ((__half2*)out)[2 * i] = h0;
    ((__half2*)out)[2 * i + 1] = h1;
}

// W fp32 [k][256] -> fp16 [n][kd] (transpose + convert); writes coalesced
__global__ void cvt_w16_kernel(const float* __restrict__ W,
                               __half* __restrict__ out, int kd) {
    int i = blockIdx.x * blockDim.x + threadIdx.x;
    if (i >= 256 * kd) return;
    int n = i / kd, k = i - n * kd;
    out[i] = __float2half_rn(W[(size_t)k * 256 + n]);
}

// ---------------------------------------------------------------------------
__global__ void zero_int_kernel(int* __restrict__ p, int n) {
    for (int i = blockIdx.x * blockDim.x + threadIdx.x; i < n;
         i += gridDim.x * blockDim.x)
        p[i] = 0;
}

__global__ void count_kernel(const int* __restrict__ dst, int* __restrict__ cnt,
                             int nE) {
    for (int e = blockIdx.x * blockDim.x + threadIdx.x; e < nE;
         e += gridDim.x * blockDim.x)
        atomicAdd(&cnt[dst[e]], 1);
}

__global__ __launch_bounds__(256) void scan_block_kernel(
        int* __restrict__ data, int* __restrict__ aux, int n) {
    __shared__ int wsum[8];
    int t = threadIdx.x;
    int base = blockIdx.x * 1024 + t * 4;
    int v[4];
#pragma unroll
    for (int k = 0; k < 4; k++) v[k] = (base + k < n) ? data[base + k] : 0;
    int tsum = v[0] + v[1] + v[2] + v[3];
    int lane = t & 31, wid = t >> 5;
    int x = tsum;
#pragma unroll
    for (int o = 1; o < 32; o <<= 1) {
        int y = __shfl_up_sync(0xffffffffu, x, o);
        if (lane >= o) x += y;
    }
    int wexc = x - tsum;
    if (lane == 31) wsum[wid] = x;
    __syncthreads();
    if (t == 0) {
        int run = 0;
#pragma unroll
        for (int i = 0; i < 8; i++) { int s = wsum[i]; wsum[i] = run; run += s; }
        aux[blockIdx.x] = run;
    }
    __syncthreads();
    int run = wsum[wid] + wexc;
#pragma unroll
    for (int k = 0; k < 4; k++) {
        if (base + k < n) data[base + k] = run;
        run += v[k];
    }
}

__global__ void scan_aux_kernel(int* __restrict__ aux, int nb,
                                int* __restrict__ total) {
    int lane = threadIdx.x;
    int base = lane * 4;
    int v[4];
#pragma unroll
    for (int k = 0; k < 4; k++) v[k] = (base + k < nb) ? aux[base + k] : 0;
    int tsum = v[0] + v[1] + v[2] + v[3];
    int x = tsum;
#pragma unroll
    for (int o = 1; o < 32; o <<= 1) {
        int y = __shfl_up_sync(0xffffffffu, x, o);
        if (lane >= o) x += y;
    }
    int run = x - tsum;
#pragma unroll
    for (int k = 0; k < 4; k++) {
        int t = v[k];
        if (base + k < nb) aux[base + k] = run;
        run += t;
    }
    if (lane == 31) *total = x;
}

__global__ void finalize_kernel(int* __restrict__ offs, const int* __restrict__ aux,
                                int* __restrict__ cur, int n,
                                const int* __restrict__ total) {
    int i = blockIdx.x * blockDim.x + threadIdx.x;
    if (i < n) {
        int v = offs[i] + aux[i >> 10];
        offs[i] = v;
        cur[i] = v;
    }
    if (i == 0) offs[n] = *total;
}

__global__ void fill_kernel(const int* __restrict__ src, const int* __restrict__ dst,
                            int* __restrict__ cur, int* __restrict__ eid, int nE) {
    for (int e = blockIdx.x * blockDim.x + threadIdx.x; e < nE;
         e += gridDim.x * blockDim.x) {
        int p = atomicAdd(&cur[dst[e]], 1);
        eid[p] = src[e];
    }
}

// warp per dst: msg16[d] = mean(feat16[src]) over bucket (0 if empty).
// One uint4 (8 halves) per lane covers the 256-half row.
__global__ __launch_bounds__(256) void gather16_kernel(
        const __half* __restrict__ feat, const int* __restrict__ offs,
        const int* __restrict__ eid, __half* __restrict__ msg, int n) {
    int w = (blockIdx.x * blockDim.x + threadIdx.x) >> 5;
    int lane = threadIdx.x & 31;
    if (w >= n) return;
    int s0 = __ldg(offs + w), s1 = __ldg(offs + w + 1);
    float acc[8];
#pragma unroll
    for (int q = 0; q < 8; q++) acc[q] = 0.f;
    int j = s0;
    for (; j + 1 < s1; j += 2) {
        int e0 = __ldg(eid + j), e1 = __ldg(eid + j + 1);
        uint4 u0 = __ldg((const uint4*)(feat + (size_t)e0 * D) + lane);
        uint4 u1 = __ldg((const uint4*)(feat + (size_t)e1 * D) + lane);
        const __half2* p0 = (const __half2*)&u0;
        const __half2* p1 = (const __half2*)&u1;
#pragma unroll
        for (int q = 0; q < 4; q++) {
            float2 f0 = __half22float2(p0[q]);
            float2 f1 = __half22float2(p1[q]);
            acc[2 * q] += f0.x + f1.x;
            acc[2 * q + 1] += f0.y + f1.y;
        }
    }
    if (j < s1) {
        int e0 = __ldg(eid + j);
        uint4 u0 = __ldg((const uint4*)(feat + (size_t)e0 * D) + lane);
        const __half2* p0 = (const __half2*)&u0;
#pragma unroll
        for (int q = 0; q < 4; q++) {
            float2 f0 = __half22float2(p0[q]);
            acc[2 * q] += f0.x;
            acc[2 * q + 1] += f0.y;
        }
    }
    float r = 1.f / (float)max(s1 - s0, 1);
    uint4 ov;
    __half2* po = (__half2*)&ov;
#pragma unroll
    for (int q = 0; q < 4; q++)
        po[q] = __floats2half2_rn(acc[2 * q] * r, acc[2 * q + 1] * r);
    ((uint4*)(msg + (size_t)w * D))[lane] = ov;
}

// ---------------------------------------------------------------------------
__device__ __forceinline__ void mma_f16(float* c, const unsigned* a,
                                        unsigned b0, unsigned b1) {
    asm volatile(
        "mma.sync.aligned.m16n8k16.row.col.f32.f16.f16.f32 "
        "{%0,%1,%2,%3}, {%4,%5,%6,%7}, {%8,%9}, {%0,%1,%2,%3};"
        : "+f"(c[0]), "+f"(c[1]), "+f"(c[2]), "+f"(c[3])
        : "r"(a[0]), "r"(a[1]), "r"(a[2]), "r"(a[3]), "r"(b0), "r"(b1));
}

__device__ __forceinline__ unsigned ldh2(const __half* p) {
    return *reinterpret_cast<const unsigned*>(p);
}

__device__ __forceinline__ void cp16(unsigned dst, const void* src, int nbytes) {
    asm volatile("cp.async.cg.shared.global [%0], [%1], 16, %2;"
                 :: "r"(dst), "l"(src), "r"(nbytes));
}
__device__ __forceinline__ void cp_commit() {
    asm volatile("cp.async.commit_group;");
}
template <int N>
__device__ __forceinline__ void cp_wait() {
    asm volatile("cp.async.wait_group %0;" :: "n"(N));
}

// ---------------------------------------------------------------------------
// Fused fp16-MMA MLP: out = [h16|msg16] @ W1h + b1 -> relu -> @ W2h + b2
// -> + hres -> (LN). 64x256 per block, 8 warps (2wm x 4wn, m=32 n=64/warp),
// m16n8k16.f16.f32 MMA, cp.async double-buffered, 2 CTAs/SM.
// W tiles are [n][k] fp16 so every fragment load is one half2 LDS.
__global__ __launch_bounds__(256, 2) void mlp16_kernel(
    const __half* __restrict__ hA,
    const __half* __restrict__ msgA,
    const float* __restrict__ hres,
    const __half* __restrict__ w1h, const float* __restrict__ b1,
    const __half* __restrict__ w2h, const float* __restrict__ b2,
    const float* __restrict__ lng, const float* __restrict__ lnb,
    float* __restrict__ out, __half* __restrict__ out16, int M, int use_ln)
{
    extern __shared__ __half smh[];
    __half* As  = smh;                 // [2][64][PAH]
    __half* Bs  = smh + SM_BS_H;       // [2][256][PBH]
    __half* hid = smh + SM_HID_H;      // [64][PHH]
    unsigned sbase = (unsigned)__cvta_generic_to_shared(smh);
    unsigned As_s = sbase;
    unsigned Bs_s = sbase + SM_BS_H * 2;

    int tid = threadIdx.x;
    int lane = tid & 31, w = tid >> 5;
    int grp = lane >> 2, tig = lane & 3;
    int wm = w & 1, wn = w >> 1;
    int m0 = wm * 32;
    int nbase = wn * 64;
    int row0 = blockIdx.x * BM;

    float acc[2][8][4];
#pragma unroll
    for (int mt = 0; mt < 2; mt++)
#pragma unroll
        for (int i = 0; i < 8; i++)
#pragma unroll
            for (int j = 0; j < 4; j++) acc[mt][i][j] = 0.f;

    // cp.async producer indices. A: 64 rows x 32B (tid<128); B: 256 rows x 32B.
    int arow = tid >> 1, achunk = tid & 1;
    int aval = (row0 + arow < M) ? 16 : 0;
    int arowc = (row0 + arow < M) ? (row0 + arow) : (M - 1);
    unsigned a_dst0 = As_s + (unsigned)(arow * PAH + 8 * achunk) * 2;
    unsigned b_dst0 = Bs_s + (unsigned)(tid * PBH) * 2;

    auto issueA = [&](int s, int buf) {
        if (tid >= 128) return;
        int k0 = s * KT;
        const __half* srcp = (k0 < D)
            ? (hA   + (size_t)arowc * D + k0 + 8 * achunk)
            : (msgA + (size_t)arowc * D + (k0 - D) + 8 * achunk);
        cp16(a_dst0 + buf * (ASZH * 2), srcp, aval);
    };
    auto issueB = [&](const __half* __restrict__ Wh, int s, int buf, int kd) {
        const __half* srcp = Wh + (size_t)tid * kd + s * KT;
        unsigned dst = b_dst0 + buf * (BSZH * 2);
        cp16(dst, srcp, 16);
        cp16(dst + 16, srcp + 8, 16);
    };

    auto computeStep = [&](const __half* __restrict__ Ah, int astrideH,
                           int kbaseH, const __half* __restrict__ Bh) {
        int c0 = kbaseH + 2 * tig;
        unsigned a0[4], a1[4];
        a0[0] = ldh2(Ah + (m0 + grp) * astrideH + c0);
        a0[1] = ldh2(Ah + (m0 + grp + 8) * astrideH + c0);
        a0[2] = ldh2(Ah + (m0 + grp) * astrideH + c0 + 8);
        a0[3] = ldh2(Ah + (m0 + grp + 8) * astrideH + c0 + 8);
        a1[0] = ldh2(Ah + (m0 + grp + 16) * astrideH + c0);
        a1[1] = ldh2(Ah + (m0 + grp + 24) * astrideH + c0);
        a1[2] = ldh2(Ah + (m0 + grp + 16) * astrideH + c0 + 8);
        a1[3] = ldh2(Ah + (m0 + grp + 24) * astrideH + c0 + 8);
#pragma unroll
        for (int t2 = 0; t2 < 8; t2++) {
            int n = nbase + 8 * t2 + grp;
            unsigned b0 = ldh2(Bh + n * PBH + 2 * tig);
            unsigned b1 = ldh2(Bh + n * PBH + 2 * tig + 8);
            mma_f16(acc[0][t2], a0, b0, b1);
            mma_f16(acc[1][t2], a1, b0, b1);
        }
    };

    // ---- phase 1: hidden = relu(x @ W1 + b1), K = 512, 32 steps ----
    issueA(0, 0); issueB(w1h, 0, 0, 512); cp_commit();
#pragma unroll 1
    for (int s = 0; s < 32; s++) {
        cp_wait<0>();
        __syncthreads();
        if (s < 31) { issueA(s + 1, (s + 1) & 1); issueB(w1h, s + 1, (s + 1) & 1, 512); }
        else        { issueB(w2h, 0, 0, 256); }   // prefetch first W2 tile
        cp_commit();
        computeStep(As + (s & 1) * ASZH, PAH, 0, Bs + (s & 1) * BSZH);
    }

    // epilogue 1: bias + relu -> hid (fp16 half2 stores); reset acc
#pragma unroll
    for (int mt = 0; mt < 2; mt++)
#pragma unroll
    for (int t2 = 0; t2 < 8; t2++) {
        int c = nbase + 8 * t2 + 2 * tig;
        int mr = m0 + 16 * mt + grp;
        float bb0 = __ldg(b1 + c), bb1 = __ldg(b1 + c + 1);
        __half2 h0 = __floats2half2_rn(fmaxf(acc[mt][t2][0] + bb0, 0.f),
                                       fmaxf(acc[mt][t2][1] + bb1, 0.f));
        __half2 h1 = __floats2half2_rn(fmaxf(acc[mt][t2][2] + bb0, 0.f),
                                       fmaxf(acc[mt][t2][3] + bb1, 0.f));
        *(__half2*)(hid + mr * PHH + c) = h0;
        *(__half2*)(hid + (mr + 8) * PHH + c) = h1;
#pragma unroll
        for (int j = 0; j < 4; j++) acc[mt][t2][j] = 0.f;
    }

    // ---- phase 2: acc = hid @ W2, K = 256, 16 steps ----
#pragma unroll 1
    for (int s = 0; s < 16; s++) {
        cp_wait<0>();
        __syncthreads();   // s==0: publishes epilogue-1 hid writes + W2 tile 0
        if (s < 15) { issueB(w2h, s + 1, (s + 1) & 1, 256); cp_commit(); }
        computeStep(hid, PHH, s * KT, Bs + (s & 1) * BSZH);
    }
    __syncthreads();   // all hid reads done before overwrite

    // epilogue 2: raw acc -> hid (fp16)
#pragma unroll
    for (int mt = 0; mt < 2; mt++)
#pragma unroll
    for (int t2 = 0; t2 < 8; t2++) {
        int c = nbase + 8 * t2 + 2 * tig;
        int mr = m0 + 16 * mt + grp;
        *(__half2*)(hid + mr * PHH + c) =
            __floats2half2_rn(acc[mt][t2][0], acc[mt][t2][1]);
        *(__half2*)(hid + (mr + 8) * PHH + c) =
            __floats2half2_rn(acc[mt][t2][2], acc[mt][t2][3]);
    }
    __syncthreads();

    // output pass: + b2 + residual (+ LN); warp w owns rows 8w..8w+7
    for (int q = 0; q < 8; q++) {
        int r = w * 8 + q;
        int row = row0 + r;
        if (row >= M) continue;
        float v[8];
        float sum = 0.f, sq = 0.f;
#pragma unroll
        for (int j = 0; j < 8; j++) {
            int c = lane + 32 * j;
            float x = __half2float(hid[r * PHH + c]) + __ldg(b2 + c)
                      + hres[(size_t)row * D + c];
            v[j] = x; sum += x; sq += x * x;
        }
        if (use_ln) {
#pragma unroll
            for (int o = 16; o > 0; o >>= 1) {
                sum += __shfl_xor_sync(0xffffffffu, sum, o);
                sq  += __shfl_xor_sync(0xffffffffu, sq, o);
            }
            float mean = sum * (1.f / D);
            float var  = sq * (1.f / D) - mean * mean;
            float rstd = rsqrtf(var + 1e-5f);
#pragma unroll
            for (int j = 0; j < 8; j++) {
                int c = lane + 32 * j;
                v[j] = (v[j] - mean) * rstd * __ldg(lng + c) + __ldg(lnb + c);
            }
        }
#pragma unroll
        for (int j = 0; j < 8; j++) {
            int c = lane + 32 * j;
            out[(size_t)row * D + c] = v[j];
            if (out16) out16[(size_t)row * D + c] = __float2half_rn(v[j]);
        }
    }
}

// ---------------------------------------------------------------------------
static inline int cdiv(int a, int b) { return (a + b - 1) / b; }

struct Scratch {
    __half *ch16, *nh16, *on16, *tp16, *mg16, *w1h, *w2h;
    float *tmp;
    int *offs, *cur, *eid, *aux, *total;
};

static void buildCSRAndGather(const __half* feat16, const int* src,
                              const int* dst, int nE, int n, const Scratch& S) {
    int nb = cdiv(n, 1024);
    zero_int_kernel<<<cdiv(n + 1, 256), 256>>>(S.offs, n + 1);
    count_kernel<<<cdiv(nE, 256), 256>>>(dst, S.offs, nE);
    scan_block_kernel<<<nb, 256>>>(S.offs, S.aux, n);
    scan_aux_kernel<<<1, 32>>>(S.aux, nb, S.total);
    finalize_kernel<<<cdiv(n, 256), 256>>>(S.offs, S.aux, S.cur, n, S.total);
    fill_kernel<<<cdiv(nE, 256), 256>>>(src, dst, S.cur, S.eid, nE);
    gather16_kernel<<<cdiv(n * 32, 256), 256>>>(feat16, S.offs, S.eid, S.mg16, n);
}

extern "C" void kernel_launch(void* const* d_in, const int* in_sizes, int n_in,
                              void* d_out, int out_size) {
    const float* cell_h = (const float*)d_in[0];
    const float* net_h  = (const float*)d_in[1];
    const int* e_c2n = (const int*)d_in[2];
    const int* e_n2c = (const int*)d_in[3];
    const int* e_c2c = (const int*)d_in[4];
    const float* c2n_w1 = (const float*)d_in[5];
    const float* c2n_b1 = (const float*)d_in[6];
    const float* c2n_w2 = (const float*)d_in[7];
    const float* c2n_b2 = (const float*)d_in[8];
    const float* n2c_w1 = (const float*)d_in[9];
    const float* n2c_b1 = (const float*)d_in[10];
    const float* n2c_w2 = (const float*)d_in[11];
    const float* n2c_b2 = (const float*)d_in[12];
    const float* c2c_w1 = (const float*)d_in[13];
    const float* c2c_b1 = (const float*)d_in[14];
    const float* c2c_w2 = (const float*)d_in[15];
    const float* c2c_b2 = (const float*)d_in[16];
    const float* net_ln_g  = (const float*)d_in[17];
    const float* net_ln_b  = (const float*)d_in[18];
    const float* cell_ln_g = (const float*)d_in[19];
    const float* cell_ln_b = (const float*)d_in[20];

    int n_cell = in_sizes[0] / D;
    int n_net  = in_sizes[1] / D;
    int E1 = in_sizes[2] / 2;
    int E2 = in_sizes[3] / 2;
    int E3 = in_sizes[4] / 2;

    float* out = (float*)d_out;
    float* out_cell = out;
    float* out_net  = out + (size_t)n_cell * D;

    static Scratch S = {};
    if (!S.tmp) {
        cudaGetSymbolAddress((void**)&S.ch16, g_ch16);
        cudaGetSymbolAddress((void**)&S.nh16, g_nh16);
        cudaGetSymbolAddress((void**)&S.on16, g_on16);
        cudaGetSymbolAddress((void**)&S.tp16, g_tp16);
        cudaGetSymbolAddress((void**)&S.mg16, g_mg16);
        cudaGetSymbolAddress((void**)&S.w1h, g_w1h);
        cudaGetSymbolAddress((void**)&S.w2h, g_w2h);
        cudaGetSymbolAddress((void**)&S.tmp, g_tmp);
        cudaGetSymbolAddress((void**)&S.offs, g_offs);
        cudaGetSymbolAddress((void**)&S.cur, g_cur);
        cudaGetSymbolAddress((void**)&S.eid, g_eid);
        cudaGetSymbolAddress((void**)&S.aux, g_aux);
        cudaGetSymbolAddress((void**)&S.total, g_total);
        cudaFuncSetAttribute(mlp16_kernel,
                             cudaFuncAttributeMaxDynamicSharedMemorySize,
                             SMEM_BYTES);
    }

    // fp16 copies of the input features
    cvt_h16_kernel<<<cdiv(n_cell * D / 4, 256), 256>>>(cell_h, S.ch16,
                                                       n_cell * D / 4);
    cvt_h16_kernel<<<cdiv(n_net * D / 4, 256), 256>>>(net_h, S.nh16,
                                                      n_net * D / 4);

    // Stage 1: cells -> nets, net_h' = LN(net_h + MLP([net_h, mean_msg]))
    cvt_w16_kernel<<<cdiv(256 * 512, 256), 256>>>(c2n_w1, S.w1h, 512);
    cvt_w16_kernel<<<cdiv(256 * 256, 256), 256>>>(c2n_w2, S.w2h, 256);
    buildCSRAndGather(S.ch16, e_c2n, e_c2n + E1, E1, n_net, S);
    mlp16_kernel<<<cdiv(n_net, BM), 256, SMEM_BYTES>>>(
        S.nh16, S.mg16, net_h, S.w1h, c2n_b1, S.w2h, c2n_b2,
        net_ln_g, net_ln_b, out_net, S.on16, n_net, 1);

    // Stage 2: nets -> cells, cell_tmp = cell_h + MLP([cell_h, mean_msg])
    cvt_w16_kernel<<<cdiv(256 * 512, 256), 256>>>(n2c_w1, S.w1h, 512);
    cvt_w16_kernel<<<cdiv(256 * 256, 256), 256>>>(n2c_w2, S.w2h, 256);
    buildCSRAndGather(S.on16, e_n2c, e_n2c + E2, E2, n_cell, S);
    mlp16_kernel<<<cdiv(n_cell, BM), 256, SMEM_BYTES>>>(
        S.ch16, S.mg16, cell_h, S.w1h, n2c_b1, S.w2h, n2c_b2,
        (const float*)0, (const float*)0, S.tmp, S.tp16, n_cell, 0);

    // Stage 3: cells -> cells, cell_h' = LN(cell_tmp + MLP([cell_tmp, mean_msg]))
    cvt_w16_kernel<<<cdiv(256 * 512, 256), 256>>>(c2c_w1, S.w1h, 512);
    cvt_w16_kernel<<<cdiv(256 * 256, 256), 256>>>(c2c_w2, S.w2h, 256);
    buildCSRAndGather(S.tp16, e_c2c, e_c2c + E3, E3, n_cell, S);
    mlp16_kernel<<<cdiv(n_cell, BM), 256, SMEM_BYTES>>>(
        S.tp16, S.mg16, S.tmp, S.w1h, c2c_b1, S.w2h, c2c_b2,
        cell_ln_g, cell_ln_b, out_cell, (__half*)0, n_cell, 1);
}

// round 15
// speedup vs baseline: 1.5562x; 1.5562x over previous
#include <cuda_runtime.h>
#include <cuda_fp16.h>

#define D 256
#define MAXN 100000
#define MAXNET 50176
#define MAXE 301056
#define BM 64
#define KT 16
#define STG 4
#define PAH 24       // A row stride (halves): word 12g+t -> conflict-free
#define PBH 24       // B row stride (halves): word 12n+t -> conflict-free
#define PHH 264      // hid row stride (halves): word 132m -> 4g+t distinct

#define ASZH (BM * PAH)       // 1536 halves per A buffer
#define BSZH (256 * PBH)      // 6144 halves per B buffer
#define HIDH (BM * PHH)       // 16896 halves
#define SM_BS_H (STG * ASZH)
#define SM_HID_H (STG * ASZH + STG * BSZH)
#define SMEM_BYTES ((STG * ASZH + STG * BSZH + HIDH) * 2)   // 95232 B

// Scratch (allocation-free rule: __device__ globals)
__device__ __half g_ch16[(size_t)MAXN * D];
__device__ __half g_nh16[(size_t)MAXNET * D];
__device__ __half g_on16[(size_t)MAXNET * D];
__device__ __half g_tp16[(size_t)MAXN * D];
__device__ __half g_mg16[(size_t)MAXN * D];
__device__ __half g_w1h[3 * 512 * 256];         // W1 fp16 [n][k], 3 stages
__device__ __half g_w2h[3 * 256 * 256];         // W2 fp16 [n][k], 3 stages
__device__ float  g_tmp[(size_t)MAXN * D];
__device__ int    g_offs[3 * (MAXN + 1)];
__device__ int    g_cur[3 * MAXN];
__device__ int    g_eid[3 * MAXE];
__device__ int    g_aux[3 * 128];
__device__ int    g_total[3];

// ---------------------------------------------------------------------------
// both feature arrays fp32 -> fp16 in one launch (y=0 cell, y=1 net)
__global__ void cvt_feat_kernel(const float* __restrict__ a, __half* __restrict__ oa,
                                int n4a,
                                const float* __restrict__ b, __half* __restrict__ ob,
                                int n4b) {
    const float* in = blockIdx.y ? b : a;
    __half* out = blockIdx.y ? ob : oa;
    int n4 = blockIdx.y ? n4b : n4a;
    int i = blockIdx.x * blockDim.x + threadIdx.x;
    if (i >= n4) return;
    float4 v = ((const float4*)in)[i];
    ((__half2*)out)[2 * i]     = __floats2half2_rn(v.x, v.y);
    ((__half2*)out)[2 * i + 1] = __floats2half2_rn(v.z, v.w);
}

// all 6 weight matrices fp32 [k][256] -> fp16 [n][kd] in one launch
__global__ void cvt_w_all_kernel(const float* __restrict__ w1a,
                                 const float* __restrict__ w1b,
                                 const float* __restrict__ w1c,
                                 const float* __restrict__ w2a,
                                 const float* __restrict__ w2b,
                                 const float* __restrict__ w2c,
                                 __half* __restrict__ o1, __half* __restrict__ o2) {
    int y = blockIdx.y;
    const float* W;
    __half* out;
    int kd;
    if (y < 3) {
        W = (y == 0) ? w1a : (y == 1) ? w1b : w1c;
        out = o1 + (size_t)y * 512 * 256;
        kd = 512;
    } else {
        int z = y - 3;
        W = (z == 0) ? w2a : (z == 1) ? w2b : w2c;
        out = o2 + (size_t)z * 256 * 256;
        kd = 256;
    }
    int i = blockIdx.x * blockDim.x + threadIdx.x;
    if (i >= 256 * kd) return;
    int n = i / kd, k = i - n * kd;
    out[i] = __float2half_rn(W[(size_t)k * 256 + n]);
}

// ---------------------------------------------------------------------------
// batched CSR build: blockIdx.y = graph id (0..2)
__global__ void zero3_kernel(int* o0, int* o1, int* o2, int n0, int n1, int n2) {
    int y = blockIdx.y;
    int* p = (y == 0) ? o0 : (y == 1) ? o1 : o2;
    int n = (y == 0) ? n0 : (y == 1) ? n1 : n2;
    for (int i = blockIdx.x * blockDim.x + threadIdx.x; i < n;
         i += gridDim.x * blockDim.x)
        p[i] = 0;
}

__global__ void count3_kernel(const int* d0, const int* d1, const int* d2,
                              int* c0, int* c1, int* c2,
                              int e0, int e1, int e2) {
    int y = blockIdx.y;
    const int* d = (y == 0) ? d0 : (y == 1) ? d1 : d2;
    int* c = (y == 0) ? c0 : (y == 1) ? c1 : c2;
    int nE = (y == 0) ? e0 : (y == 1) ? e1 : e2;
    for (int e = blockIdx.x * blockDim.x + threadIdx.x; e < nE;
         e += gridDim.x * blockDim.x)
        atomicAdd(&c[d[e]], 1);
}

__global__ __launch_bounds__(256) void scan_block3_kernel(
        int* o0, int* o1, int* o2, int* __restrict__ aux,
        int n0, int n1, int n2) {
    __shared__ int wsum[8];
    int y = blockIdx.y;
    int* data = (y == 0) ? o0 : (y == 1) ? o1 : o2;
    int n = (y == 0) ? n0 : (y == 1) ? n1 : n2;
    int t = threadIdx.x;
    int base = blockIdx.x * 1024 + t * 4;
    int v[4];
#pragma unroll
    for (int k = 0; k < 4; k++) v[k] = (base + k < n) ? data[base + k] : 0;
    int tsum = v[0] + v[1] + v[2] + v[3];
    int lane = t & 31, wid = t >> 5;
    int x = tsum;
#pragma unroll
    for (int o = 1; o < 32; o <<= 1) {
        int yv = __shfl_up_sync(0xffffffffu, x, o);
        if (lane >= o) x += yv;
    }
    int wexc = x - tsum;
    if (lane == 31) wsum[wid] = x;
    __syncthreads();
    if (t == 0) {
        int run = 0;
#pragma unroll
        for (int i = 0; i < 8; i++) { int s = wsum[i]; wsum[i] = run; run += s; }
        aux[y * 128 + blockIdx.x] = run;
    }
    __syncthreads();
    int run = wsum[wid] + wexc;
#pragma unroll
    for (int k = 0; k < 4; k++) {
        if (base + k < n) data[base + k] = run;
        run += v[k];
    }
}

// one block, 96 threads: warp y scans aux[y*128 .. ] (nb_y <= 128)
__global__ void scan_aux3_kernel(int* __restrict__ aux, int nb0, int nb1, int nb2,
                                 int* __restrict__ total) {
    int wy = threadIdx.x >> 5, lane = threadIdx.x & 31;
    int nb = (wy == 0) ? nb0 : (wy == 1) ? nb1 : nb2;
    int* a = aux + wy * 128;
    int base = lane * 4;
    int v[4];
#pragma unroll
    for (int k = 0; k < 4; k++) v[k] = (base + k < nb) ? a[base + k] : 0;
    int tsum = v[0] + v[1] + v[2] + v[3];
    int x = tsum;
#pragma unroll
    for (int o = 1; o < 32; o <<= 1) {
        int yv = __shfl_up_sync(0xffffffffu, x, o);
        if (lane >= o) x += yv;
    }
    int run = x - tsum;
#pragma unroll
    for (int k = 0; k < 4; k++) {
        int t = v[k];
        if (base + k < nb) a[base + k] = run;
        run += t;
    }
    if (lane == 31) total[wy] = x;
}

__global__ void finalize3_kernel(int* o0, int* o1, int* o2,
                                 int* c0, int* c1, int* c2,
                                 const int* __restrict__ aux,
                                 const int* __restrict__ total,
                                 int n0, int n1, int n2) {
    int y = blockIdx.y;
    int* offs = (y == 0) ? o0 : (y == 1) ? o1 : o2;
    int* cur = (y == 0) ? c0 : (y == 1) ? c1 : c2;
    int n = (y == 0) ? n0 : (y == 1) ? n1 : n2;
    int i = blockIdx.x * blockDim.x + threadIdx.x;
    if (i < n) {
        int v = offs[i] + aux[y * 128 + (i >> 10)];
        offs[i] = v;
        cur[i] = v;
    }
    if (i == 0) offs[n] = total[y];
}

__global__ void fill3_kernel(const int* s0, const int* s1, const int* s2,
                             const int* d0, const int* d1, const int* d2,
                             int* c0, int* c1, int* c2,
                             int* i0, int* i1, int* i2,
                             int e0, int e1, int e2) {
    int y = blockIdx.y;
    const int* src = (y == 0) ? s0 : (y == 1) ? s1 : s2;
    const int* dst = (y == 0) ? d0 : (y == 1) ? d1 : d2;
    int* cur = (y == 0) ? c0 : (y == 1) ? c1 : c2;
    int* eid = (y == 0) ? i0 : (y == 1) ? i1 : i2;
    int nE = (y == 0) ? e0 : (y == 1) ? e1 : e2;
    for (int e = blockIdx.x * blockDim.x + threadIdx.x; e < nE;
         e += gridDim.x * blockDim.x) {
        int p = atomicAdd(&cur[dst[e]], 1);
        eid[p] = src[e];
    }
}

// warp per dst: msg16[d] = mean(feat16[src]) over bucket (0 if empty)
__global__ __launch_bounds__(256) void gather16_kernel(
        const __half* __restrict__ feat, const int* __restrict__ offs,
        const int* __restrict__ eid, __half* __restrict__ msg, int n) {
    int w = (blockIdx.x * blockDim.x + threadIdx.x) >> 5;
    int lane = threadIdx.x & 31;
    if (w >= n) return;
    int s0 = __ldg(offs + w), s1 = __ldg(offs + w + 1);
    float acc[8];
#pragma unroll
    for (int q = 0; q < 8; q++) acc[q] = 0.f;
    int j = s0;
    for (; j + 1 < s1; j += 2) {
        int e0 = __ldg(eid + j), e1 = __ldg(eid + j + 1);
        uint4 u0 = __ldg((const uint4*)(feat + (size_t)e0 * D) + lane);
        uint4 u1 = __ldg((const uint4*)(feat + (size_t)e1 * D) + lane);
        const __half2* p0 = (const __half2*)&u0;
        const __half2* p1 = (const __half2*)&u1;
#pragma unroll
        for (int q = 0; q < 4; q++) {
            float2 f0 = __half22float2(p0[q]);
            float2 f1 = __half22float2(p1[q]);
            acc[2 * q] += f0.x + f1.x;
            acc[2 * q + 1] += f0.y + f1.y;
        }
    }
    if (j < s1) {
        int e0 = __ldg(eid + j);
        uint4 u0 = __ldg((const uint4*)(feat + (size_t)e0 * D) + lane);
        const __half2* p0 = (const __half2*)&u0;
#pragma unroll
        for (int q = 0; q < 4; q++) {
            float2 f0 = __half22float2(p0[q]);
            acc[2 * q] += f0.x;
            acc[2 * q + 1] += f0.y;
        }
    }
    float r = 1.f / (float)max(s1 - s0, 1);
    uint4 ov;
    __half2* po = (__half2*)&ov;
#pragma unroll
    for (int q = 0; q < 4; q++)
        po[q] = __floats2half2_rn(acc[2 * q] * r, acc[2 * q + 1] * r);
    ((uint4*)(msg + (size_t)w * D))[lane] = ov;
}

// ---------------------------------------------------------------------------
__device__ __forceinline__ void mma_f16(float* c, const unsigned* a,
                                        unsigned b0, unsigned b1) {
    asm volatile(
        "mma.sync.aligned.m16n8k16.row.col.f32.f16.f16.f32 "
        "{%0,%1,%2,%3}, {%4,%5,%6,%7}, {%8,%9}, {%0,%1,%2,%3};"
        : "+f"(c[0]), "+f"(c[1]), "+f"(c[2]), "+f"(c[3])
        : "r"(a[0]), "r"(a[1]), "r"(a[2]), "r"(a[3]), "r"(b0), "r"(b1));
}

__device__ __forceinline__ unsigned ldh2(const __half* p) {
    return *reinterpret_cast<const unsigned*>(p);
}

__device__ __forceinline__ void cp16(unsigned dst, const void* src, int nbytes) {
    asm volatile("cp.async.cg.shared.global [%0], [%1], 16, %2;"
                 :: "r"(dst), "l"(src), "r"(nbytes));
}
__device__ __forceinline__ void cp_commit() {
    asm volatile("cp.async.commit_group;");
}
template <int N>
__device__ __forceinline__ void cp_wait() {
    asm volatile("cp.async.wait_group %0;" :: "n"(N));
}

// ---------------------------------------------------------------------------
// Fused fp16-MMA MLP with 4-stage cp.async pipeline (wait_group<2>, 3 tiles
// in flight): step time no longer bound by single-tile GMEM latency.
// 64x256 per block, 8 warps (2wm x 4wn), m16n8k16.f16.f32, 2 CTAs/SM.
__global__ __launch_bounds__(256, 2) void mlp16_kernel(
    const __half* __restrict__ hA,
    const __half* __restrict__ msgA,
    const float* __restrict__ hres,
    const __half* __restrict__ w1h, const float* __restrict__ b1,
    const __half* __restrict__ w2h, const float* __restrict__ b2,
    const float* __restrict__ lng, const float* __restrict__ lnb,
    float* __restrict__ out, __half* __restrict__ out16, int M, int use_ln)
{
    extern __shared__ __half smh[];
    __half* As  = smh;                 // [STG][64][PAH]
    __half* Bs  = smh + SM_BS_H;       // [STG][256][PBH]
    __half* hid = smh + SM_HID_H;      // [64][PHH]
    unsigned sbase = (unsigned)__cvta_generic_to_shared(smh);
    unsigned As_s = sbase;
    unsigned Bs_s = sbase + SM_BS_H * 2;

    int tid = threadIdx.x;
    int lane = tid & 31, w = tid >> 5;
    int grp = lane >> 2, tig = lane & 3;
    int wm = w & 1, wn = w >> 1;
    int m0 = wm * 32;
    int nbase = wn * 64;
    int row0 = blockIdx.x * BM;

    float acc[2][8][4];
#pragma unroll
    for (int mt = 0; mt < 2; mt++)
#pragma unroll
        for (int i = 0; i < 8; i++)
#pragma unroll
            for (int j = 0; j < 4; j++) acc[mt][i][j] = 0.f;

    int arow = tid >> 1, achunk = tid & 1;
    int aval = (row0 + arow < M) ? 16 : 0;
    int arowc = (row0 + arow < M) ? (row0 + arow) : (M - 1);
    unsigned a_dst0 = As_s + (unsigned)(arow * PAH + 8 * achunk) * 2;
    unsigned b_dst0 = Bs_s + (unsigned)(tid * PBH) * 2;

    auto issueA = [&](int s, int buf) {
        if (tid >= 128) return;
        int k0 = s * KT;
        const __half* srcp = (k0 < D)
            ? (hA   + (size_t)arowc * D + k0 + 8 * achunk)
            : (msgA + (size_t)arowc * D + (k0 - D) + 8 * achunk);
        cp16(a_dst0 + buf * (ASZH * 2), srcp, aval);
    };
    auto issueB = [&](const __half* __restrict__ Wh, int s, int buf, int kd) {
        const __half* srcp = Wh + (size_t)tid * kd + s * KT;
        unsigned dst = b_dst0 + buf * (BSZH * 2);
        cp16(dst, srcp, 16);
        cp16(dst + 16, srcp + 8, 16);
    };

    auto computeStep = [&](const __half* __restrict__ Ah, int astrideH,
                           int kbaseH, const __half* __restrict__ Bh) {
        int c0 = kbaseH + 2 * tig;
        unsigned a0[4], a1[4];
        a0[0] = ldh2(Ah + (m0 + grp) * astrideH + c0);
        a0[1] = ldh2(Ah + (m0 + grp + 8) * astrideH + c0);
        a0[2] = ldh2(Ah + (m0 + grp) * astrideH + c0 + 8);
        a0[3] = ldh2(Ah + (m0 + grp + 8) * astrideH + c0 + 8);
        a1[0] = ldh2(Ah + (m0 + grp + 16) * astrideH + c0);
        a1[1] = ldh2(Ah + (m0 + grp + 24) * astrideH + c0);
        a1[2] = ldh2(Ah + (m0 + grp + 16) * astrideH + c0 + 8);
        a1[3] = ldh2(Ah + (m0 + grp + 24) * astrideH + c0 + 8);
#pragma unroll
        for (int t2 = 0; t2 < 8; t2++) {
            int n = nbase + 8 * t2 + grp;
            unsigned b0 = ldh2(Bh + n * PBH + 2 * tig);
            unsigned b1 = ldh2(Bh + n * PBH + 2 * tig + 8);
            mma_f16(acc[0][t2], a0, b0, b1);
            mma_f16(acc[1][t2], a1, b0, b1);
        }
    };

    // ---- phase 1: hidden = relu(x @ W1 + b1), K = 512, 32 steps ----
    // prologue: 3 tiles in flight
#pragma unroll
    for (int p = 0; p < 3; p++) {
        issueA(p, p); issueB(w1h, p, p, 512); cp_commit();
    }
#pragma unroll 1
    for (int s = 0; s < 32; s++) {
        cp_wait<2>();          // tile s complete (<=2 groups outstanding)
        __syncthreads();
        int nx = s + 3;
        if (nx < 32)      { issueA(nx, nx & 3); issueB(w1h, nx, nx & 3, 512); }
        else if (nx < 35) { issueB(w2h, nx - 32, nx & 3, 256); }  // W2 tiles 0..2
        cp_commit();           // empty groups keep accounting uniform
        computeStep(As + (s & 3) * ASZH, PAH, 0, Bs + (s & 3) * BSZH);
    }

    // epilogue 1: bias + relu -> hid (fp16); reset acc. W2 tiles stream in.
#pragma unroll
    for (int mt = 0; mt < 2; mt++)
#pragma unroll
    for (int t2 = 0; t2 < 8; t2++) {
        int c = nbase + 8 * t2 + 2 * tig;
        int mr = m0 + 16 * mt + grp;
        float bb0 = __ldg(b1 + c), bb1 = __ldg(b1 + c + 1);
        *(__half2*)(hid + mr * PHH + c) =
            __floats2half2_rn(fmaxf(acc[mt][t2][0] + bb0, 0.f),
                              fmaxf(acc[mt][t2][1] + bb1, 0.f));
        *(__half2*)(hid + (mr + 8) * PHH + c) =
            __floats2half2_rn(fmaxf(acc[mt][t2][2] + bb0, 0.f),
                              fmaxf(acc[mt][t2][3] + bb1, 0.f));
#pragma unroll
        for (int j = 0; j < 4; j++) acc[mt][t2][j] = 0.f;
    }

    // ---- phase 2: acc = hid @ W2, K = 256, 16 steps ----
#pragma unroll 1
    for (int s = 0; s < 16; s++) {
        cp_wait<2>();          // W2 tile s complete
        __syncthreads();       // s==0: also publishes epilogue-1 hid writes
        int nx = s + 3;
        if (nx < 16) issueB(w2h, nx, nx & 3, 256);
        cp_commit();
        computeStep(hid, PHH, s * KT, Bs + (s & 3) * BSZH);
    }
    __syncthreads();   // all hid reads done before overwrite

    // epilogue 2: raw acc -> hid (fp16)
#pragma unroll
    for (int mt = 0; mt < 2; mt++)
#pragma unroll
    for (int t2 = 0; t2 < 8; t2++) {
        int c = nbase + 8 * t2 + 2 * tig;
        int mr = m0 + 16 * mt + grp;
        *(__half2*)(hid + mr * PHH + c) =
            __floats2half2_rn(acc[mt][t2][0], acc[mt][t2][1]);
        *(__half2*)(hid + (mr + 8) * PHH + c) =
            __floats2half2_rn(acc[mt][t2][2], acc[mt][t2][3]);
    }
    __syncthreads();

    // output pass: + b2 + residual (+ LN); warp w owns rows 8w..8w+7
    for (int q = 0; q < 8; q++) {
        int r = w * 8 + q;
        int row = row0 + r;
        if (row >= M) continue;
        float v[8];
        float sum = 0.f, sq = 0.f;
#pragma unroll
        for (int j = 0; j < 8; j++) {
            int c = lane + 32 * j;
            float x = __half2float(hid[r * PHH + c]) + __ldg(b2 + c)
                      + hres[(size_t)row * D + c];
            v[j] = x; sum += x; sq += x * x;
        }
        if (use_ln) {
#pragma unroll
            for (int o = 16; o > 0; o >>= 1) {
                sum += __shfl_xor_sync(0xffffffffu, sum, o);
                sq  += __shfl_xor_sync(0xffffffffu, sq, o);
            }
            float mean = sum * (1.f / D);
            float var  = sq * (1.f / D) - mean * mean;
            float rstd = rsqrtf(var + 1e-5f);
#pragma unroll
            for (int j = 0; j < 8; j++) {
                int c = lane + 32 * j;
                v[j] = (v[j] - mean) * rstd * __ldg(lng + c) + __ldg(lnb + c);
            }
        }
#pragma unroll
        for (int j = 0; j < 8; j++) {
            int c = lane + 32 * j;
            out[(size_t)row * D + c] = v[j];
            if (out16) out16[(size_t)row * D + c] = __float2half_rn(v[j]);
        }
    }
}

// ---------------------------------------------------------------------------
static inline int cdiv(int a, int b) { return (a + b - 1) / b; }

extern "C" void kernel_launch(void* const* d_in, const int* in_sizes, int n_in,
                              void* d_out, int out_size) {
    const float* cell_h = (const float*)d_in[0];
    const float* net_h  = (const float*)d_in[1];
    const int* e_c2n = (const int*)d_in[2];
    const int* e_n2c = (const int*)d_in[3];
    const int* e_c2c = (const int*)d_in[4];
    const float* c2n_w1 = (const float*)d_in[5];
    const float* c2n_b1 = (const float*)d_in[6];
    const float* c2n_w2 = (const float*)d_in[7];
    const float* c2n_b2 = (const float*)d_in[8];
    const float* n2c_w1 = (const float*)d_in[9];
    const float* n2c_b1 = (const float*)d_in[10];
    const float* n2c_w2 = (const float*)d_in[11];
    const float* n2c_b2 = (const float*)d_in[12];
    const float* c2c_w1 = (const float*)d_in[13];
    const float* c2c_b1 = (const float*)d_in[14];
    const float* c2c_w2 = (const float*)d_in[15];
    const float* c2c_b2 = (const float*)d_in[16];
    const float* net_ln_g  = (const float*)d_in[17];
    const float* net_ln_b  = (const float*)d_in[18];
    const float* cell_ln_g = (const float*)d_in[19];
    const float* cell_ln_b = (const float*)d_in[20];

    int n_cell = in_sizes[0] / D;
    int n_net  = in_sizes[1] / D;
    int E1 = in_sizes[2] / 2;
    int E2 = in_sizes[3] / 2;
    int E3 = in_sizes[4] / 2;

    float* out = (float*)d_out;
    float* out_cell = out;
    float* out_net  = out + (size_t)n_cell * D;

    static __half *ch16, *nh16, *on16, *tp16, *mg16, *w1h, *w2h;
    static float* tmp;
    static int *offs, *cur, *eid, *aux, *total;
    static bool init = false;
    if (!init) {
        cudaGetSymbolAddress((void**)&ch16, g_ch16);
        cudaGetSymbolAddress((void**)&nh16, g_nh16);
        cudaGetSymbolAddress((void**)&on16, g_on16);
        cudaGetSymbolAddress((void**)&tp16, g_tp16);
        cudaGetSymbolAddress((void**)&mg16, g_mg16);
        cudaGetSymbolAddress((void**)&w1h, g_w1h);
        cudaGetSymbolAddress((void**)&w2h, g_w2h);
        cudaGetSymbolAddress((void**)&tmp, g_tmp);
        cudaGetSymbolAddress((void**)&offs, g_offs);
        cudaGetSymbolAddress((void**)&cur, g_cur);
        cudaGetSymbolAddress((void**)&eid, g_eid);
        cudaGetSymbolAddress((void**)&aux, g_aux);
        cudaGetSymbolAddress((void**)&total, g_total);
        cudaFuncSetAttribute(mlp16_kernel,
                             cudaFuncAttributeMaxDynamicSharedMemorySize,
                             SMEM_BYTES);
        init = true;
    }
    int* of0 = offs;
    int* of1 = offs + (MAXN + 1);
    int* of2 = offs + 2 * (MAXN + 1);
    int* cu0 = cur, *cu1 = cur + MAXN, *cu2 = cur + 2 * MAXN;
    int* ei0 = eid, *ei1 = eid + MAXE, *ei2 = eid + 2 * MAXE;
    __half* w1a = w1h;
    __half* w1b = w1h + (size_t)512 * 256;
    __half* w1c = w1h + (size_t)2 * 512 * 256;
    __half* w2a = w2h;
    __half* w2b = w2h + (size_t)256 * 256;
    __half* w2c = w2h + (size_t)2 * 256 * 256;

    // ---- converts (batched) ----
    {
        dim3 g(cdiv(n_cell * D / 4, 256), 2);
        cvt_feat_kernel<<<g, 256>>>(cell_h, ch16, n_cell * D / 4,
                                    net_h, nh16, n_net * D / 4);
    }
    {
        dim3 g(512, 6);
        cvt_w_all_kernel<<<g, 256>>>(c2n_w1, n2c_w1, c2c_w1,
                                     c2n_w2, n2c_w2, c2c_w2, w1h, w2h);
    }

    // ---- all 3 CSR builds, batched (edges only, no feature deps) ----
    {
        dim3 g(cdiv(n_cell + 1, 256), 3);
        zero3_kernel<<<g, 256>>>(of0, of1, of2, n_net + 1, n_cell + 1, n_cell + 1);
    }
    {
        dim3 g(cdiv(E1, 256), 3);
        count3_kernel<<<g, 256>>>(e_c2n + E1, e_n2c + E2, e_c2c + E3,
                                  of0, of1, of2, E1, E2, E3);
    }
    {
        dim3 g(cdiv(n_cell, 1024), 3);
        scan_block3_kernel<<<g, 256>>>(of0, of1, of2, aux, n_net, n_cell, n_cell);
    }
    scan_aux3_kernel<<<1, 96>>>(aux, cdiv(n_net, 1024), cdiv(n_cell, 1024),
                                cdiv(n_cell, 1024), total);
    {
        dim3 g(cdiv(n_cell, 256), 3);
        finalize3_kernel<<<g, 256>>>(of0, of1, of2, cu0, cu1, cu2, aux, total,
                                     n_net, n_cell, n_cell);
    }
    {
        dim3 g(cdiv(E1, 256), 3);
        fill3_kernel<<<g, 256>>>(e_c2n, e_n2c, e_c2c,
                                 e_c2n + E1, e_n2c + E2, e_c2c + E3,
                                 cu0, cu1, cu2, ei0, ei1, ei2, E1, E2, E3);
    }

    // Stage 1: cells -> nets, net_h' = LN(net_h + MLP([net_h, mean_msg]))
    gather16_kernel<<<cdiv(n_net * 32, 256), 256>>>(ch16, of0, ei0, mg16, n_net);
    mlp16_kernel<<<cdiv(n_net, BM), 256, SMEM_BYTES>>>(
        nh16, mg16, net_h, w1a, c2n_b1, w2a, c2n_b2,
        net_ln_g, net_ln_b, out_net, on16, n_net, 1);

    // Stage 2: nets -> cells, cell_tmp = cell_h + MLP([cell_h, mean_msg])
    gather16_kernel<<<cdiv(n_cell * 32, 256), 256>>>(on16, of1, ei1, mg16, n_cell);
    mlp16_kernel<<<cdiv(n_cell, BM), 256, SMEM_BYTES>>>(
        ch16, mg16, cell_h, w1b, n2c_b1, w2b, n2c_b2,
        (const float*)0, (const float*)0, tmp, tp16, n_cell, 0);

    // Stage 3: cells -> cells, cell_h' = LN(cell_tmp + MLP([cell_tmp, mean_msg]))
    gather16_kernel<<<cdiv(n_cell * 32, 256), 256>>>(tp16, of2, ei2, mg16, n_cell);
    mlp16_kernel<<<cdiv(n_cell, BM), 256, SMEM_BYTES>>>(
        tp16, mg16, tmp, w1c, c2c_b1, w2c, c2c_b2,
        cell_ln_g, cell_ln_b, out_cell, (__half*)0, n_cell, 1);
}